// round 5
// baseline (speedup 1.0000x reference)
#include <cuda_runtime.h>
#include <cuda_bf16.h>

// Problem constants (fixed by reference)
#define BN    4096
#define NTOTN 100000
#define DN    32
#define HN    64
#define TN    8
#define NEGV  (-1e9f)

// One warp per batch element. 4 warps / block. Shared: padded key tile
// (stride 65 -> conflict-free stage/read/broadcast) + hidden vector.
__global__ __launch_bounds__(128, 4)
void gfn_rollout_kernel(const float* __restrict__ q,          // [B,64]
                        const int*   __restrict__ nbr,        // [NTOT,32]
                        const int*   __restrict__ start,      // [B]
                        const void*  __restrict__ evp,        // [NTOT,32] bool (dtype detected)
                        const float* __restrict__ keys,       // [NTOT,32,64]
                        const float* __restrict__ Wi,         // [64,64]
                        const float* __restrict__ Wh,         // [64,64]
                        const float* __restrict__ Wk,         // [64,64]
                        const float* __restrict__ g,          // [66]
                        const float* __restrict__ be,         // [66]
                        const float* __restrict__ sw,         // [66]
                        const float* __restrict__ sbp,        // [1]
                        const float* __restrict__ temp,       // [1]
                        float* __restrict__ out)
{
    __shared__ float skeys[4][DN * 65];
    __shared__ float shid[4][HN];

    const int w    = threadIdx.x >> 5;
    const int lane = threadIdx.x & 31;
    const int b    = blockIdx.x * 4 + w;

    float* sk = skeys[w];
    float* sh = shid[w];

    const float tclamp = fmaxf(temp[0], 1e-5f);
    const float stop_b = sbp[0];

    // ---- detect edge_valid element width (word-typed int32/float32 vs byte bool).
    // A byte-bool array reinterpreted as words has top-3-bytes==0 with prob 1/8
    // per word; 128 samples -> misclassification prob ~(1/8)^128 ~= 0.
    bool word_typed;
    {
        const unsigned* wv = (const unsigned*)evp;
        bool ok = true;
        #pragma unroll
        for (int i = 0; i < 4; i++) {
            unsigned v = wv[i * 32 + lane];
            ok &= (v == 0u || v == 1u || v == 0x3F800000u);
        }
        word_typed = __all_sync(0xffffffffu, ok);
    }
    const unsigned*      ev32 = (const unsigned*)evp;
    const unsigned char* ev8  = (const unsigned char*)evp;

    // ---- init hidden = tanh(q[b] @ W_init) ----
    sh[lane]      = q[b * HN + lane];
    sh[lane + 32] = q[b * HN + lane + 32];
    __syncwarp();
    {
        float a0 = 0.f, a1 = 0.f;
        #pragma unroll
        for (int i = 0; i < HN; i++) {
            float hv = sh[i];
            a0 += hv * __ldg(&Wi[i * HN + lane]);
            a1 += hv * __ldg(&Wi[i * HN + lane + 32]);
        }
        __syncwarp();
        sh[lane]      = tanhf(a0);
        sh[lane + 32] = tanhf(a1);
        __syncwarp();
    }

    int   curr     = start[b];
    float lp_total = 0.f;
    int   nmoves   = 0;

    // output sections (float32, concatenated reference outputs)
    float* outA   = out;                          // actions_seq  [B,9]
    float* outTot = out + BN * 9;                 // log_pf_total [B]
    float* outS   = out + BN * 9 + BN;            // log_pf_steps [B,9]
    float* outNM  = out + BN * 9 + BN + BN * 9;   // num_moves    [B]

    int t = 0;
    for (t = 0; t <= TN; t++) {
        // ---- stage keys[curr] (8KB) into shared (float4 LDG), stride-65 padded ----
        const float4* kb4 = (const float4*)(keys + (size_t)curr * (DN * HN));
        #pragma unroll
        for (int it = 0; it < 16; it++) {
            int f = it * 32 + lane;            // float4 index 0..511
            float4 v = __ldg(&kb4[f]);
            int d = f >> 4;                    // 16 float4 per key row
            int h = (f & 15) << 2;
            float* dst = sk + d * 65 + h;
            dst[0] = v.x; dst[1] = v.y; dst[2] = v.z; dst[3] = v.w;
        }
        __syncwarp();

        // ---- validity (lane == edge slot d) ----
        size_t evi = (size_t)curr * DN + lane;
        int vraw = word_typed ? (ev32[evi] != 0u) : (ev8[evi] != 0);
        int vd = (t < TN) ? vraw : 0;
        unsigned vm = __ballot_sync(0xffffffffu, vd);
        float has_edge = vm ? 1.f : 0.f;

        // ---- scores: lane d dots hidden with key row d ----
        float sc = 0.f;
        const float* row = sk + lane * 65;
        #pragma unroll
        for (int h = 0; h < HN; h++)
            sc += sh[h] * row[h];
        float logit = (vd ? sc : NEGV) / tclamp;

        // ---- layernorm(66) + stop logit ----
        float x0 = sh[lane], x1 = sh[lane + 32];
        float e64 = (float)t / (float)TN;
        float e65 = has_edge;
        float ssum = x0 + x1 + (lane == 0 ? (e64 + e65) : 0.f);
        #pragma unroll
        for (int o = 16; o; o >>= 1) ssum += __shfl_xor_sync(~0u, ssum, o);
        float mu = ssum * (1.f / 66.f);
        float c0 = x0 - mu, c1 = x1 - mu;
        float vsum = c0 * c0 + c1 * c1 +
                     (lane == 0 ? ((e64 - mu) * (e64 - mu) + (e65 - mu) * (e65 - mu)) : 0.f);
        #pragma unroll
        for (int o = 16; o; o >>= 1) vsum += __shfl_xor_sync(~0u, vsum, o);
        float rstd = rsqrtf(vsum * (1.f / 66.f) + 1e-5f);
        float dsum = (c0 * rstd * __ldg(&g[lane])      + __ldg(&be[lane]))      * __ldg(&sw[lane])
                   + (c1 * rstd * __ldg(&g[lane + 32]) + __ldg(&be[lane + 32])) * __ldg(&sw[lane + 32]);
        if (lane == 0) {
            dsum += ((e64 - mu) * rstd * __ldg(&g[64]) + __ldg(&be[64])) * __ldg(&sw[64]);
            dsum += ((e65 - mu) * rstd * __ldg(&g[65]) + __ldg(&be[65])) * __ldg(&sw[65]);
        }
        #pragma unroll
        for (int o = 16; o; o >>= 1) dsum += __shfl_xor_sync(~0u, dsum, o);
        float stop_logit = (dsum + stop_b) / tclamp;

        // ---- argmax (first-max) over 32 edge logits, then stop (strict >) ----
        float bv = logit; int bi = lane;
        #pragma unroll
        for (int o = 16; o; o >>= 1) {
            float ov = __shfl_xor_sync(~0u, bv, o);
            int   oi = __shfl_xor_sync(~0u, bi, o);
            if (ov > bv || (ov == bv && oi < bi)) { bv = ov; bi = oi; }
        }
        int action; float chosen;
        if (stop_logit > bv) { action = DN; chosen = stop_logit; }
        else                 { action = bi; chosen = bv; }

        // ---- log-softmax denominator over 33 ----
        float m = fmaxf(bv, stop_logit);
        float es = expf(logit - m);
        #pragma unroll
        for (int o = 16; o; o >>= 1) es += __shfl_xor_sync(~0u, es, o);
        es += expf(stop_logit - m);
        float lp = chosen - (m + logf(es));

        bool chose_stop = (action == DN);
        int  a = chose_stop ? (DN - 1) : action;
        int  act_rec = chose_stop ? -1 : curr * DN + a;

        if (lane == 0) {
            outA[b * 9 + t] = (float)act_rec;
            outS[b * 9 + t] = lp;
        }
        lp_total += lp;
        if (chose_stop) break;
        nmoves++;

        // ---- advance: hidden = tanh(h @ Wh + keys[a] @ Wk), curr = tail ----
        int tail = __ldg(&nbr[(size_t)curr * DN + a]);
        const float* selrow = sk + a * 65;
        float u0 = 0.f, u1 = 0.f;
        #pragma unroll
        for (int i = 0; i < HN; i++) {
            float hv = sh[i];
            float sv = selrow[i];
            u0 += hv * __ldg(&Wh[i * HN + lane])      + sv * __ldg(&Wk[i * HN + lane]);
            u1 += hv * __ldg(&Wh[i * HN + lane + 32]) + sv * __ldg(&Wk[i * HN + lane + 32]);
        }
        __syncwarp();
        sh[lane]      = tanhf(u0);
        sh[lane + 32] = tanhf(u1);
        __syncwarp();
        curr = tail;
    }

    // ---- fill forced-stopped tail steps + totals ----
    if (lane == 0) {
        for (int tt = t + 1; tt <= TN; tt++) {
            outA[b * 9 + tt] = -1.f;
            outS[b * 9 + tt] = 0.f;
        }
        outTot[b] = lp_total;
        outNM[b]  = (float)nmoves;
    }
}

extern "C" void kernel_launch(void* const* d_in, const int* in_sizes, int n_in,
                              void* d_out, int out_size)
{
    const float* q     = (const float*)d_in[0];
    const int*   nbr   = (const int*)d_in[1];
    const int*   start = (const int*)d_in[2];
    const void*  ev    = (const void*)d_in[3];
    const float* keys  = (const float*)d_in[4];
    const float* Wi    = (const float*)d_in[5];
    const float* Wh    = (const float*)d_in[6];
    const float* Wk    = (const float*)d_in[7];
    const float* g     = (const float*)d_in[8];
    const float* be    = (const float*)d_in[9];
    const float* sw    = (const float*)d_in[10];
    const float* sb    = (const float*)d_in[11];
    const float* temp  = (const float*)d_in[12];
    float* out = (float*)d_out;

    dim3 grid(BN / 4);
    dim3 block(128);
    gfn_rollout_kernel<<<grid, block>>>(q, nbr, start, ev, keys,
                                        Wi, Wh, Wk, g, be, sw, sb, temp, out);
}

// round 6
// speedup vs baseline: 1.3702x; 1.3702x over previous
#include <cuda_runtime.h>
#include <cuda_bf16.h>

// Problem constants (fixed by reference)
#define BN    4096
#define NTOTN 100000
#define DN    32
#define HN    64
#define TN    8
#define NEGV  (-1e9f)

// One warp per batch element, 4 warps/block.
// Lane layout: q = lane&15 (chunk / output-column group), h = lane>>4 (row parity).
// Scores: lane ends holding score of edge row  myrow = 2q + h.
// Matvec: lane (q, h) accumulates output chunk [4q..4q+3] over rows i with i&1 == h.
__global__ __launch_bounds__(128, 6)
void gfn_rollout_kernel(const float* __restrict__ qt,         // [B,64]
                        const int*   __restrict__ nbr,        // [NTOT,32]
                        const int*   __restrict__ start,      // [B]
                        const void*  __restrict__ evp,        // [NTOT,32] bool (dtype detected)
                        const float* __restrict__ keys,       // [NTOT,32,64]
                        const float* __restrict__ Wi,         // [64,64]
                        const float* __restrict__ Wh,         // [64,64]
                        const float* __restrict__ Wk,         // [64,64]
                        const float* __restrict__ g,          // [66]
                        const float* __restrict__ be,         // [66]
                        const float* __restrict__ sw,         // [66]
                        const float* __restrict__ sbp,        // [1]
                        const float* __restrict__ temp,       // [1]
                        float* __restrict__ out)
{
    __shared__ float shid[4][HN];   // hidden per warp
    __shared__ float ssel[4][HN];   // selected key row per warp

    const int w     = threadIdx.x >> 5;
    const int lane  = threadIdx.x & 31;
    const int q     = lane & 15;
    const int h     = lane >> 4;
    const int myrow = 2 * q + h;
    const int b     = blockIdx.x * 4 + w;

    float* sh = shid[w];
    float* ss = ssel[w];

    const float tclamp = fmaxf(temp[0], 1e-5f);
    const float itc    = 1.0f / tclamp;
    const float stop_b = sbp[0];

    // ---- detect edge_valid element width (word-typed int32/float32 vs byte bool) ----
    bool word_typed;
    {
        const unsigned* wv = (const unsigned*)evp;
        bool ok = true;
        #pragma unroll
        for (int i = 0; i < 4; i++) {
            unsigned v = wv[i * 32 + lane];
            ok &= (v == 0u || v == 1u || v == 0x3F800000u);
        }
        word_typed = __all_sync(0xffffffffu, ok);
    }
    const unsigned*      ev32 = (const unsigned*)evp;
    const unsigned char* ev8  = (const unsigned char*)evp;

    // ---- init hidden = tanh(q[b] @ W_init), cooperative row-major matvec ----
    sh[lane]      = qt[b * HN + lane];
    sh[lane + 32] = qt[b * HN + lane + 32];
    __syncwarp();
    {
        float4 acc = make_float4(0.f, 0.f, 0.f, 0.f);
        #pragma unroll
        for (int it = 0; it < 32; it++) {
            int i = 2 * it + h;
            float hv = sh[i];
            float4 wv = __ldg((const float4*)(Wi + i * HN + 4 * q));
            acc.x += hv * wv.x; acc.y += hv * wv.y;
            acc.z += hv * wv.z; acc.w += hv * wv.w;
        }
        acc.x += __shfl_xor_sync(0xffffffffu, acc.x, 16);
        acc.y += __shfl_xor_sync(0xffffffffu, acc.y, 16);
        acc.z += __shfl_xor_sync(0xffffffffu, acc.z, 16);
        acc.w += __shfl_xor_sync(0xffffffffu, acc.w, 16);
        __syncwarp();
        if (h == 0) {
            float4 t4 = make_float4(tanhf(acc.x), tanhf(acc.y), tanhf(acc.z), tanhf(acc.w));
            *(float4*)(sh + 4 * q) = t4;
        }
        __syncwarp();
    }

    int   curr     = start[b];
    float lp_total = 0.f;
    int   nmoves   = 0;

    // output sections (float32, concatenated reference outputs)
    float* outA   = out;                          // actions_seq  [B,9]
    float* outTot = out + BN * 9;                 // log_pf_total [B]
    float* outS   = out + BN * 9 + BN;            // log_pf_steps [B,9]
    float* outNM  = out + BN * 9 + BN + BN * 9;   // num_moves    [B]

    int t = 0;
    for (t = 0; t <= TN; t++) {
        const float4* kb4 = (const float4*)(keys + (size_t)curr * (DN * HN));

        // ---- fused gather + partial dots: p[it] = <keys[2it+h], hidden>[chunk q] ----
        float4 h4 = *(const float4*)(sh + 4 * q);   // broadcast within halves
        float p[16];
        #pragma unroll
        for (int it = 0; it < 16; it++) {
            float4 v = __ldg(&kb4[it * 32 + lane]);
            p[it] = v.x * h4.x + v.y * h4.y + v.z * h4.z + v.w * h4.w;
        }

        // ---- transpose-reduce over chunks (within each 16-lane half) ----
        // After: lane (q,h) holds full score of row 2q+h in p[0].
        #pragma unroll
        for (int k = 8; k >= 1; k >>= 1) {
            bool hi = (q & k) != 0;
            #pragma unroll
            for (int i = 0; i < 8; i++) {
                if (i < k) {
                    float send = hi ? p[i] : p[i + k];
                    float recv = __shfl_xor_sync(0xffffffffu, send, k);
                    p[i] = (hi ? p[i + k] : p[i]) + recv;
                }
            }
        }
        float sc = p[0];

        // ---- validity (lane owns edge slot myrow) ----
        size_t evi = (size_t)curr * DN + myrow;
        int vraw = word_typed ? (ev32[evi] != 0u) : (ev8[evi] != 0);
        int vd = (t < TN) ? vraw : 0;
        unsigned vm = __ballot_sync(0xffffffffu, vd);
        float has_edge = vm ? 1.f : 0.f;
        float logit = (vd ? sc : NEGV) * itc;

        // ---- layernorm(66) + stop logit ----
        float x0 = sh[lane], x1 = sh[lane + 32];
        float e64 = (float)t / (float)TN;
        float e65 = has_edge;
        float ssum = x0 + x1 + (lane == 0 ? (e64 + e65) : 0.f);
        #pragma unroll
        for (int o = 16; o; o >>= 1) ssum += __shfl_xor_sync(~0u, ssum, o);
        float mu = ssum * (1.f / 66.f);
        float c0 = x0 - mu, c1 = x1 - mu;
        float vsum = c0 * c0 + c1 * c1 +
                     (lane == 0 ? ((e64 - mu) * (e64 - mu) + (e65 - mu) * (e65 - mu)) : 0.f);
        #pragma unroll
        for (int o = 16; o; o >>= 1) vsum += __shfl_xor_sync(~0u, vsum, o);
        float rstd = rsqrtf(vsum * (1.f / 66.f) + 1e-5f);
        float dsum = (c0 * rstd * __ldg(&g[lane])      + __ldg(&be[lane]))      * __ldg(&sw[lane])
                   + (c1 * rstd * __ldg(&g[lane + 32]) + __ldg(&be[lane + 32])) * __ldg(&sw[lane + 32]);
        if (lane == 0) {
            dsum += ((e64 - mu) * rstd * __ldg(&g[64]) + __ldg(&be[64])) * __ldg(&sw[64]);
            dsum += ((e65 - mu) * rstd * __ldg(&g[65]) + __ldg(&be[65])) * __ldg(&sw[65]);
        }
        #pragma unroll
        for (int o = 16; o; o >>= 1) dsum += __shfl_xor_sync(~0u, dsum, o);
        float stop_logit = (dsum + stop_b) * itc;

        // ---- argmax (first-max by row id) over 32 edge logits, then stop (strict >) ----
        float bv = logit; int bi = myrow;
        #pragma unroll
        for (int o = 16; o; o >>= 1) {
            float ov = __shfl_xor_sync(~0u, bv, o);
            int   oi = __shfl_xor_sync(~0u, bi, o);
            if (ov > bv || (ov == bv && oi < bi)) { bv = ov; bi = oi; }
        }
        int action; float chosen;
        if (stop_logit > bv) { action = DN; chosen = stop_logit; }
        else                 { action = bi; chosen = bv; }

        // ---- log-softmax denominator over 33 ----
        float m = fmaxf(bv, stop_logit);
        float es = expf(logit - m);
        #pragma unroll
        for (int o = 16; o; o >>= 1) es += __shfl_xor_sync(~0u, es, o);
        es += expf(stop_logit - m);
        float lp = chosen - (m + logf(es));

        bool chose_stop = (action == DN);
        int  a = chose_stop ? (DN - 1) : action;
        int  act_rec = chose_stop ? -1 : curr * DN + a;

        if (lane == 0) {
            outA[b * 9 + t] = (float)act_rec;
            outS[b * 9 + t] = lp;
        }
        lp_total += lp;
        if (chose_stop) break;
        nmoves++;

        // ---- advance: hidden = tanh(h @ Wh + sel @ Wk), curr = tail ----
        int tail = __ldg(&nbr[(size_t)curr * DN + a]);
        float4 selv = __ldg(&kb4[a * 16 + q]);   // chunk q of chosen row (L1-hot)
        if (h == 0) *(float4*)(ss + 4 * q) = selv;
        __syncwarp();

        float4 acc = make_float4(0.f, 0.f, 0.f, 0.f);
        #pragma unroll
        for (int it = 0; it < 32; it++) {
            int i = 2 * it + h;
            float hv = sh[i];
            float sv = ss[i];
            float4 wh4 = __ldg((const float4*)(Wh + i * HN + 4 * q));
            float4 wk4 = __ldg((const float4*)(Wk + i * HN + 4 * q));
            acc.x += hv * wh4.x + sv * wk4.x;
            acc.y += hv * wh4.y + sv * wk4.y;
            acc.z += hv * wh4.z + sv * wk4.z;
            acc.w += hv * wh4.w + sv * wk4.w;
        }
        acc.x += __shfl_xor_sync(0xffffffffu, acc.x, 16);
        acc.y += __shfl_xor_sync(0xffffffffu, acc.y, 16);
        acc.z += __shfl_xor_sync(0xffffffffu, acc.z, 16);
        acc.w += __shfl_xor_sync(0xffffffffu, acc.w, 16);
        __syncwarp();
        if (h == 0) {
            float4 t4 = make_float4(tanhf(acc.x), tanhf(acc.y), tanhf(acc.z), tanhf(acc.w));
            *(float4*)(sh + 4 * q) = t4;
        }
        __syncwarp();
        curr = tail;
    }

    // ---- fill forced-stopped tail steps + totals ----
    if (lane == 0) {
        for (int tt = t + 1; tt <= TN; tt++) {
            outA[b * 9 + tt] = -1.f;
            outS[b * 9 + tt] = 0.f;
        }
        outTot[b] = lp_total;
        outNM[b]  = (float)nmoves;
    }
}

extern "C" void kernel_launch(void* const* d_in, const int* in_sizes, int n_in,
                              void* d_out, int out_size)
{
    const float* q     = (const float*)d_in[0];
    const int*   nbr   = (const int*)d_in[1];
    const int*   start = (const int*)d_in[2];
    const void*  ev    = (const void*)d_in[3];
    const float* keys  = (const float*)d_in[4];
    const float* Wi    = (const float*)d_in[5];
    const float* Wh    = (const float*)d_in[6];
    const float* Wk    = (const float*)d_in[7];
    const float* g     = (const float*)d_in[8];
    const float* be    = (const float*)d_in[9];
    const float* sw    = (const float*)d_in[10];
    const float* sb    = (const float*)d_in[11];
    const float* temp  = (const float*)d_in[12];
    float* out = (float*)d_out;

    dim3 grid(BN / 4);
    dim3 block(128);
    gfn_rollout_kernel<<<grid, block>>>(q, nbr, start, ev, keys,
                                        Wi, Wh, Wk, g, be, sw, sb, temp, out);
}

// round 7
// speedup vs baseline: 1.4256x; 1.0404x over previous
#include <cuda_runtime.h>
#include <cuda_bf16.h>

// Problem constants (fixed by reference)
#define BN    4096
#define NTOTN 100000
#define DN    32
#define HN    64
#define TN    8
#define NEGV  (-1e9f)

// One warp per batch element, 4 warps/block, 7 blocks/SM -> whole grid resident
// in a single wave (148*7*4 = 4144 >= 4096 warps).
// Lane layout: q = lane&15 (chunk), h = lane>>4 (row parity); myrow = 2q+h.
__global__ __launch_bounds__(128, 7)
void gfn_rollout_kernel(const float* __restrict__ qt,         // [B,64]
                        const int*   __restrict__ nbr,        // [NTOT,32]
                        const int*   __restrict__ start,      // [B]
                        const void*  __restrict__ evp,        // [NTOT,32] bool (dtype detected)
                        const float* __restrict__ keys,       // [NTOT,32,64]
                        const float* __restrict__ Wi,         // [64,64]
                        const float* __restrict__ Wh,         // [64,64]
                        const float* __restrict__ Wk,         // [64,64]
                        const float* __restrict__ g,          // [66]
                        const float* __restrict__ be,         // [66]
                        const float* __restrict__ sw,         // [66]
                        const float* __restrict__ sbp,        // [1]
                        const float* __restrict__ temp,       // [1]
                        float* __restrict__ out)
{
    __shared__ float shid[4][HN];   // hidden per warp
    __shared__ float ssel[4][HN];   // selected key row per warp

    const int w     = threadIdx.x >> 5;
    const int lane  = threadIdx.x & 31;
    const int q     = lane & 15;
    const int h     = lane >> 4;
    const int myrow = 2 * q + h;
    const int b     = blockIdx.x * 4 + w;

    float* sh = shid[w];
    float* ss = ssel[w];

    const float tclamp = fmaxf(temp[0], 1e-5f);
    const float itc    = 1.0f / tclamp;
    const float stop_b = sbp[0];

    // ---- detect edge_valid element width (word-typed int32/float32 vs byte bool) ----
    bool word_typed;
    {
        const unsigned* wv = (const unsigned*)evp;
        bool ok = true;
        #pragma unroll
        for (int i = 0; i < 4; i++) {
            unsigned v = wv[i * 32 + lane];
            ok &= (v == 0u || v == 1u || v == 0x3F800000u);
        }
        word_typed = __all_sync(0xffffffffu, ok);
    }
    const unsigned*      ev32 = (const unsigned*)evp;
    const unsigned char* ev8  = (const unsigned char*)evp;

    // ---- fold LN constants:  ((c*rstd)*g + be)*sw == rstd * c*(g*sw)  +  be*sw ----
    const float gsw0 = __ldg(&g[lane])      * __ldg(&sw[lane]);
    const float gsw1 = __ldg(&g[lane + 32]) * __ldg(&sw[lane + 32]);
    float gsw64 = 0.f, gsw65 = 0.f;
    float bsum;
    {
        float bs = __ldg(&be[lane]) * __ldg(&sw[lane])
                 + __ldg(&be[lane + 32]) * __ldg(&sw[lane + 32]);
        if (lane == 0) {
            gsw64 = __ldg(&g[64]) * __ldg(&sw[64]);
            gsw65 = __ldg(&g[65]) * __ldg(&sw[65]);
            bs += __ldg(&be[64]) * __ldg(&sw[64]) + __ldg(&be[65]) * __ldg(&sw[65]);
        }
        #pragma unroll
        for (int o = 16; o; o >>= 1) bs += __shfl_xor_sync(~0u, bs, o);
        bsum = bs;
    }

    // ---- init hidden = tanh(q[b] @ W_init), cooperative row-major matvec ----
    sh[lane]      = qt[b * HN + lane];
    sh[lane + 32] = qt[b * HN + lane + 32];
    __syncwarp();
    {
        float4 acc = make_float4(0.f, 0.f, 0.f, 0.f);
        #pragma unroll
        for (int it = 0; it < 32; it++) {
            int i = 2 * it + h;
            float hv = sh[i];
            float4 wv = __ldg((const float4*)(Wi + i * HN + 4 * q));
            acc.x += hv * wv.x; acc.y += hv * wv.y;
            acc.z += hv * wv.z; acc.w += hv * wv.w;
        }
        acc.x += __shfl_xor_sync(0xffffffffu, acc.x, 16);
        acc.y += __shfl_xor_sync(0xffffffffu, acc.y, 16);
        acc.z += __shfl_xor_sync(0xffffffffu, acc.z, 16);
        acc.w += __shfl_xor_sync(0xffffffffu, acc.w, 16);
        __syncwarp();
        if (h == 0) {
            float4 t4 = make_float4(tanhf(acc.x), tanhf(acc.y), tanhf(acc.z), tanhf(acc.w));
            *(float4*)(sh + 4 * q) = t4;
        }
        __syncwarp();
    }

    int   curr     = start[b];
    float lp_total = 0.f;
    int   nmoves   = 0;

    // output sections (float32, concatenated reference outputs)
    float* outA   = out;                          // actions_seq  [B,9]
    float* outTot = out + BN * 9;                 // log_pf_total [B]
    float* outS   = out + BN * 9 + BN;            // log_pf_steps [B,9]
    float* outNM  = out + BN * 9 + BN + BN * 9;   // num_moves    [B]

    int t = 0;
    for (t = 0; t <= TN; t++) {
        const float4* kb4 = (const float4*)(keys + (size_t)curr * (DN * HN));

        // ---- early independent loads: nbr row (tail via shuffle later) + validity ----
        int nb = __ldg(&nbr[(size_t)curr * DN + myrow]);
        size_t evi = (size_t)curr * DN + myrow;
        int vraw = word_typed ? (ev32[evi] != 0u) : (ev8[evi] != 0);

        // ---- fused gather + partial dots: p[it] = <keys[2it+h], hidden>[chunk q] ----
        float4 h4 = *(const float4*)(sh + 4 * q);
        float p[16];
        #pragma unroll
        for (int it = 0; it < 16; it++) {
            float4 v = __ldg(&kb4[it * 32 + lane]);
            p[it] = v.x * h4.x + v.y * h4.y + v.z * h4.z + v.w * h4.w;
        }

        // ---- transpose-reduce over chunks (within each 16-lane half) ----
        #pragma unroll
        for (int k = 8; k >= 1; k >>= 1) {
            bool hi = (q & k) != 0;
            #pragma unroll
            for (int i = 0; i < 8; i++) {
                if (i < k) {
                    float send = hi ? p[i] : p[i + k];
                    float recv = __shfl_xor_sync(0xffffffffu, send, k);
                    p[i] = (hi ? p[i + k] : p[i]) + recv;
                }
            }
        }
        float sc = p[0];

        int vd = (t < TN) ? vraw : 0;
        unsigned vm = __ballot_sync(0xffffffffu, vd);
        float has_edge = vm ? 1.f : 0.f;
        float logit = (vd ? sc : NEGV) * itc;

        // ---- layernorm(66) + stop logit (folded constants) ----
        float x0 = sh[lane], x1 = sh[lane + 32];
        float e64 = (float)t / (float)TN;
        float e65 = has_edge;
        float ssum = x0 + x1 + (lane == 0 ? (e64 + e65) : 0.f);
        #pragma unroll
        for (int o = 16; o; o >>= 1) ssum += __shfl_xor_sync(~0u, ssum, o);
        float mu = ssum * (1.f / 66.f);
        float c0 = x0 - mu, c1 = x1 - mu;
        float vsum = c0 * c0 + c1 * c1 +
                     (lane == 0 ? ((e64 - mu) * (e64 - mu) + (e65 - mu) * (e65 - mu)) : 0.f);
        #pragma unroll
        for (int o = 16; o; o >>= 1) vsum += __shfl_xor_sync(~0u, vsum, o);
        float rstd = rsqrtf(vsum * (1.f / 66.f) + 1e-5f);
        float dsum = c0 * gsw0 + c1 * gsw1
                   + (lane == 0 ? ((e64 - mu) * gsw64 + (e65 - mu) * gsw65) : 0.f);
        #pragma unroll
        for (int o = 16; o; o >>= 1) dsum += __shfl_xor_sync(~0u, dsum, o);
        float stop_logit = (dsum * rstd + bsum + stop_b) * itc;

        // ---- argmax (first-max by row id) over 32 edge logits, then stop (strict >) ----
        float bv = logit; int bi = myrow;
        #pragma unroll
        for (int o = 16; o; o >>= 1) {
            float ov = __shfl_xor_sync(~0u, bv, o);
            int   oi = __shfl_xor_sync(~0u, bi, o);
            if (ov > bv || (ov == bv && oi < bi)) { bv = ov; bi = oi; }
        }
        int action; float chosen;
        if (stop_logit > bv) { action = DN; chosen = stop_logit; }
        else                 { action = bi; chosen = bv; }

        // ---- log-softmax denominator over 33 ----
        float m = fmaxf(bv, stop_logit);
        float es = expf(logit - m);
        #pragma unroll
        for (int o = 16; o; o >>= 1) es += __shfl_xor_sync(~0u, es, o);
        es += expf(stop_logit - m);
        float lp = chosen - (m + logf(es));

        bool chose_stop = (action == DN);
        int  a = chose_stop ? (DN - 1) : action;
        int  act_rec = chose_stop ? -1 : curr * DN + a;

        if (lane == 0) {
            outA[b * 9 + t] = (float)act_rec;
            outS[b * 9 + t] = lp;
        }
        lp_total += lp;
        if (chose_stop) break;
        nmoves++;

        // ---- advance: hidden = tanh(h @ Wh + sel @ Wk), curr = tail (shuffle) ----
        int src_lane = (a >> 1) | ((a & 1) << 4);      // lane owning row a
        int tail = __shfl_sync(0xffffffffu, nb, src_lane);

        float4 selv = __ldg(&kb4[a * 16 + q]);          // chunk q of chosen row (L1-hot)
        if (h == 0) *(float4*)(ss + 4 * q) = selv;
        __syncwarp();

        float4 acc = make_float4(0.f, 0.f, 0.f, 0.f);
        #pragma unroll
        for (int it = 0; it < 32; it++) {
            int i = 2 * it + h;
            float hv = sh[i];
            float sv = ss[i];
            float4 wh4 = __ldg((const float4*)(Wh + i * HN + 4 * q));
            float4 wk4 = __ldg((const float4*)(Wk + i * HN + 4 * q));
            acc.x += hv * wh4.x + sv * wk4.x;
            acc.y += hv * wh4.y + sv * wk4.y;
            acc.z += hv * wh4.z + sv * wk4.z;
            acc.w += hv * wh4.w + sv * wk4.w;
        }
        acc.x += __shfl_xor_sync(0xffffffffu, acc.x, 16);
        acc.y += __shfl_xor_sync(0xffffffffu, acc.y, 16);
        acc.z += __shfl_xor_sync(0xffffffffu, acc.z, 16);
        acc.w += __shfl_xor_sync(0xffffffffu, acc.w, 16);
        __syncwarp();
        if (h == 0) {
            float4 t4 = make_float4(tanhf(acc.x), tanhf(acc.y), tanhf(acc.z), tanhf(acc.w));
            *(float4*)(sh + 4 * q) = t4;
        }
        __syncwarp();
        curr = tail;
    }

    // ---- fill forced-stopped tail steps + totals ----
    if (lane == 0) {
        for (int tt = t + 1; tt <= TN; tt++) {
            outA[b * 9 + tt] = -1.f;
            outS[b * 9 + tt] = 0.f;
        }
        outTot[b] = lp_total;
        outNM[b]  = (float)nmoves;
    }
}

extern "C" void kernel_launch(void* const* d_in, const int* in_sizes, int n_in,
                              void* d_out, int out_size)
{
    const float* q     = (const float*)d_in[0];
    const int*   nbr   = (const int*)d_in[1];
    const int*   start = (const int*)d_in[2];
    const void*  ev    = (const void*)d_in[3];
    const float* keys  = (const float*)d_in[4];
    const float* Wi    = (const float*)d_in[5];
    const float* Wh    = (const float*)d_in[6];
    const float* Wk    = (const float*)d_in[7];
    const float* g     = (const float*)d_in[8];
    const float* be    = (const float*)d_in[9];
    const float* sw    = (const float*)d_in[10];
    const float* sb    = (const float*)d_in[11];
    const float* temp  = (const float*)d_in[12];
    float* out = (float*)d_out;

    dim3 grid(BN / 4);
    dim3 block(128);
    gfn_rollout_kernel<<<grid, block>>>(q, nbr, start, ev, keys,
                                        Wi, Wh, Wk, g, be, sw, sb, temp, out);
}